// round 14
// baseline (speedup 1.0000x reference)
#include <cuda_runtime.h>
#include <cuda_bf16.h>
#include <cuda_fp16.h>
#include <cstdint>

#define BB 2
#define CC 64
#define C8 8
#define NN 9216   // 96*96
#define L2E 1.4426950408889634f
#define VSCALE 4096.0f     // 2^12, pow2 -> exact unscale

// ---- scratch (static device globals; no allocation at runtime) ----
__device__ uint32_t g_q16[BB][4][NN];        // f16x2 pairs (ch 2pr, 2pr+1), log2e-scaled
__device__ uint32_t g_k16[BB][4][NN];        // f16x2 pairs (ch 2pr, 2pr+1)
__device__ float g_v[BB][CC][NN];
__device__ __half g_vp[BB][CC][NN];          // v' = v * rZ * 2^12  (fp16)
__device__ __half g_opart16[4][BB][CC][NN];  // partial outputs per j-quarter (f16)

// ---------------------------------------------------------------------------
// helpers
// ---------------------------------------------------------------------------
__device__ __forceinline__ uint32_t pack_f16x2(float lo, float hi) {
    uint32_t r;
    asm("cvt.rn.f16x2.f32 %0, %1, %2;" : "=r"(r) : "f"(hi), "f"(lo));
    return r;
}

__device__ __forceinline__ uint32_t ex2_h2(uint32_t h) {
    uint32_t r;
    asm("ex2.approx.f16x2 %0, %1;" : "=r"(r) : "r"(h));
    return r;
}

__device__ __forceinline__ uint32_t hadd2(uint32_t a, uint32_t b) {
    uint32_t r;
    asm("add.rn.f16x2 %0, %1, %2;" : "=r"(r) : "r"(a), "r"(b));
    return r;
}

__device__ __forceinline__ float2 h2f(uint32_t u) {
    return __half22float2(*reinterpret_cast<__half2*>(&u));
}

// energy mma: m16n8k8 f16 (A = K-tile pairs, B = q pairs, C f32)
__device__ __forceinline__ void mma_f16k8(float c[4],
                                          uint32_t a0, uint32_t a1, uint32_t b0) {
    asm volatile(
        "mma.sync.aligned.m16n8k8.row.col.f32.f16.f16.f32 "
        "{%0,%1,%2,%3}, {%4,%5}, {%6}, {%0,%1,%2,%3};"
        : "+f"(c[0]), "+f"(c[1]), "+f"(c[2]), "+f"(c[3])
        : "r"(a0), "r"(a1), "r"(b0));
}

__device__ __forceinline__ void mma_f16(float c[4],
                                        uint32_t a0, uint32_t a1, uint32_t a2, uint32_t a3,
                                        uint32_t b0, uint32_t b1) {
    asm volatile(
        "mma.sync.aligned.m16n8k16.row.col.f32.f16.f16.f32 "
        "{%0,%1,%2,%3}, {%4,%5,%6,%7}, {%8,%9}, {%0,%1,%2,%3};"
        : "+f"(c[0]), "+f"(c[1]), "+f"(c[2]), "+f"(c[3])
        : "r"(a0), "r"(a1), "r"(a2), "r"(a3), "r"(b0), "r"(b1));
}

__device__ __forceinline__ void ldsm_x4(uint32_t& r0, uint32_t& r1,
                                        uint32_t& r2, uint32_t& r3, uint32_t addr) {
    asm volatile("ldmatrix.sync.aligned.m8n8.x4.shared.b16 {%0,%1,%2,%3}, [%4];"
                 : "=r"(r0), "=r"(r1), "=r"(r2), "=r"(r3) : "r"(addr));
}

// ============================================================================
// Kernel 1: 1x1-conv projections. g=0: q(+log2e) rows 0..7 + k rows 0..7,
// stored as packed f16x2 channel-pairs; g=1..4: v rows 16(g-1).. in f32.
// ============================================================================
__global__ void __launch_bounds__(128) qkv_kernel(
    const float* __restrict__ x,
    const float* __restrict__ wq, const float* __restrict__ bq,
    const float* __restrict__ wk, const float* __restrict__ bk,
    const float* __restrict__ wv, const float* __restrict__ bv)
{
    __shared__ float sw[16][CC];
    __shared__ float sb[16];
    const int g = blockIdx.y;
    const int b = blockIdx.z;
    const int tid = threadIdx.x;

    for (int idx = tid; idx < 16 * CC; idx += 128) {
        const int row = idx >> 6, c = idx & 63;
        float val;
        if (g == 0) val = (row < 8) ? wq[row * CC + c] * L2E : wk[(row - 8) * CC + c];
        else        val = wv[(16 * (g - 1) + row) * CC + c];
        sw[row][c] = val;
    }
    if (tid < 16) {
        float bval;
        if (g == 0) bval = (tid < 8) ? bq[tid] * L2E : bk[tid - 8];
        else        bval = bv[16 * (g - 1) + tid];
        sb[tid] = bval;
    }
    __syncthreads();

    const int n0 = blockIdx.x * 256 + tid * 2;
    float2 acc[16];
    #pragma unroll
    for (int o = 0; o < 16; o++) { acc[o].x = sb[o]; acc[o].y = sb[o]; }
    const float* xb = x + (size_t)b * CC * NN;
    #pragma unroll 4
    for (int c = 0; c < CC; c++) {
        const float2 xv = *(const float2*)&xb[c * NN + n0];
        #pragma unroll
        for (int o = 0; o < 16; o++) {
            acc[o].x += sw[o][c] * xv.x;
            acc[o].y += sw[o][c] * xv.y;
        }
    }
    if (g == 0) {
        #pragma unroll
        for (int pr = 0; pr < 4; pr++) {
            uint2 qp, kp;
            qp.x = pack_f16x2(acc[2 * pr].x,     acc[2 * pr + 1].x);
            qp.y = pack_f16x2(acc[2 * pr].y,     acc[2 * pr + 1].y);
            kp.x = pack_f16x2(acc[8 + 2 * pr].x, acc[8 + 2 * pr + 1].x);
            kp.y = pack_f16x2(acc[8 + 2 * pr].y, acc[8 + 2 * pr + 1].y);
            *(uint2*)&g_q16[b][pr][n0] = qp;
            *(uint2*)&g_k16[b][pr][n0] = kp;
        }
    } else {
        const int r0 = 16 * (g - 1);
        #pragma unroll
        for (int o = 0; o < 16; o++) *(float2*)&g_v[b][r0 + o][n0] = acc[o];
    }
}

// ============================================================================
// zvpass: fused Z + v'. Block owns 64 j's, sweeps ALL i (72 chunks of 128):
// energy via f16 k8 mma (packed q/k pairs), ex2 + accumulation in f16x2,
// then rZ -> v' slice in the same kernel. grid (144, BB), block 256.
// ============================================================================
__global__ void __launch_bounds__(256) zvpass_kernel()
{
    __shared__ uint32_t skT[2][4 * 136];
    __shared__ float szw[8][64];
    __shared__ float srz[64];

    const int b = blockIdx.y;
    const int j_base = blockIdx.x * 64;
    const int tid = threadIdx.x;
    const int warp = tid >> 5, lane = tid & 31;
    const int gp = lane >> 2, tg = lane & 3;
    const int iw = warp * 16;

    // persistent q B-fragments: 8 n8 j-tiles (packed pairs, direct load)
    uint32_t Bq[8];
    #pragma unroll
    for (int nt = 0; nt < 8; nt++)
        Bq[nt] = g_q16[b][tg][j_base + nt * 8 + gp];

    uint32_t zaccH[8];
    #pragma unroll
    for (int m = 0; m < 8; m++) zaccH[m] = 0u;

    // staging: 1 uint2 per thread per chunk (4 pair-rows x 128 i)
    const int spr = tid >> 6;          // 0..3
    const int sj2 = (tid & 63) * 2;    // even
    const int NI = NN / 128;           // 72

    uint2 pre = *(const uint2*)&g_k16[b][spr][sj2];
    *(uint2*)&skT[0][spr * 136 + sj2] = pre;
    __syncthreads();

    for (int it = 0; it < NI; it++) {
        if (it + 1 < NI)
            pre = *(const uint2*)&g_k16[b][spr][(it + 1) * 128 + sj2];

        const uint32_t* buf = skT[it & 1];
        const uint32_t a0 = buf[tg * 136 + iw + gp];
        const uint32_t a1 = buf[tg * 136 + iw + gp + 8];

        #pragma unroll
        for (int nt = 0; nt < 8; nt++) {
            float e[4] = {0.f, 0.f, 0.f, 0.f};
            mma_f16k8(e, a0, a1, Bq[nt]);
            const uint32_t h01 = ex2_h2(pack_f16x2(e[0], e[1]));   // rows gp
            const uint32_t h23 = ex2_h2(pack_f16x2(e[2], e[3]));   // rows gp+8
            zaccH[nt] = hadd2(zaccH[nt], hadd2(h01, h23));
        }

        if (it + 1 < NI) {
            *(uint2*)&skT[(it + 1) & 1][spr * 136 + sj2] = pre;
            __syncthreads();
        }
    }

    // reduce over gp lanes (same tg share same j), f16x2
    #pragma unroll
    for (int nt = 0; nt < 8; nt++) {
        uint32_t v = zaccH[nt];
        v = hadd2(v, __shfl_xor_sync(~0u, v, 4));
        v = hadd2(v, __shfl_xor_sync(~0u, v, 8));
        v = hadd2(v, __shfl_xor_sync(~0u, v, 16));
        if (gp == 0) {
            const float2 f = h2f(v);
            szw[warp][nt * 8 + 2 * tg]     = f.x;
            szw[warp][nt * 8 + 2 * tg + 1] = f.y;
        }
    }
    __syncthreads();
    if (tid < 64) {
        float z = 0.f;
        #pragma unroll
        for (int w = 0; w < 8; w++) z += szw[w][tid];
        srz[tid] = VSCALE / z;
    }
    __syncthreads();

    // fused v': this block's 64-j slice
    #pragma unroll
    for (int t = 0; t < 16; t++) {
        const int idx = tid + t * 256;
        const int c = idx >> 6, jj = idx & 63;
        g_vp[b][c][j_base + jj] = __float2half(g_v[b][c][j_base + jj] * srz[jj]);
    }
}

// ============================================================================
// outpass: opart[jq][b][c][i] = sum over j-quarter of v'[c,j]*2^(q_j.k_i)
// grid (36, 4, BB), block 256, m=32/warp. Energy via f16 k8 mma on packed
// pairs; j-chunks of 384 (6 per quarter). Software-pipelined P fragments.
// ============================================================================
#define JCH 384
#define SQP32 392   // uint32 pitch (mod 32 == 8 -> conflict-free frag loads)
#define SVP 392     // f16 pitch  (row stride 196 words -> ldsm conflict-free)
#define NTT (JCH / 16)   // 24

__global__ void __launch_bounds__(256, 2) outpass_kernel()
{
    extern __shared__ float sm[];
    uint32_t* sq16 = (uint32_t*)sm;                 // [4][SQP32] packed q pairs
    __half* sv = (__half*)(sq16 + 4 * SQP32);       // [64][SVP]
    float* strans = sm;                             // epilogue overlay [64][264]

    const int b = blockIdx.z;
    const int jq = blockIdx.y;
    const int i_base = blockIdx.x * 256;
    const int tid = threadIdx.x;
    const int warp = tid >> 5, lane = tid & 31;
    const int gp = lane >> 2, tg = lane & 3;
    const int iw = warp * 32;

    // persistent K-tile A-fragments (packed f16 pairs), two m16 halves
    uint32_t ka[2][2];
    #pragma unroll
    for (int h = 0; h < 2; h++) {
        const int ib = i_base + iw + h * 16;
        ka[h][0] = g_k16[b][tg][ib + gp];
        ka[h][1] = g_k16[b][tg][ib + gp + 8];
    }

    float acc[2][8][4];
    #pragma unroll
    for (int h = 0; h < 2; h++)
        #pragma unroll
        for (int nc = 0; nc < 8; nc++)
            #pragma unroll
            for (int s = 0; s < 4; s++) acc[h][nc][s] = 0.f;

    uint32_t sv_u32;
    asm("{ .reg .u64 t; cvta.to.shared.u64 t, %1; cvt.u32.u64 %0, t; }"
        : "=r"(sv_u32) : "l"(sv));
    const int mrow = ((lane >> 4) << 3) + (lane & 7);
    const int mcol = ((lane >> 3) & 1) * 8;

    uint32_t addrp[4];
    #pragma unroll
    for (int p = 0; p < 4; p++)
        addrp[p] = sv_u32 + (uint32_t)(((p * 16 + mrow) * SVP + mcol) * 2);
    const int sqo = tg * SQP32 + gp;

    const int j0q = jq * (NN / 4);
    for (int sc = 0; sc < (NN / 4) / JCH; sc++) {
        const int jb = j0q + sc * JCH;
        __syncthreads();
        // stage packed q pairs: 4 x 384 u32 = 768 uint2
        #pragma unroll
        for (int t = 0; t < 3; t++) {
            const int seg = tid + t * 256;
            const int pr = seg / 192, j2 = (seg % 192) * 2;
            *(uint2*)&sq16[pr * SQP32 + j2] = *(const uint2*)&g_q16[b][pr][jb + j2];
        }
        // stage v': 64 x 384 f16 = 3072 uint4
        #pragma unroll
        for (int t = 0; t < 12; t++) {
            const int seg = tid + t * 256;
            const int row = seg / 48, q8 = seg % 48;
            *(uint4*)&sv[row * SVP + q8 * 8] = *(const uint4*)&g_vp[b][row][jb + q8 * 8];
        }
        __syncthreads();

        // ---- prologue: P fragments for t=0 ----
        uint32_t pac[2][4];
        {
            const uint32_t bq0 = sq16[sqo];
            const uint32_t bq1 = sq16[sqo + 8];
            #pragma unroll
            for (int h = 0; h < 2; h++) {
                float eA[4] = {0.f, 0.f, 0.f, 0.f};
                float eB[4] = {0.f, 0.f, 0.f, 0.f};
                mma_f16k8(eA, ka[h][0], ka[h][1], bq0);
                mma_f16k8(eB, ka[h][0], ka[h][1], bq1);
                pac[h][0] = ex2_h2(pack_f16x2(eA[0], eA[1]));
                pac[h][1] = ex2_h2(pack_f16x2(eA[2], eA[3]));
                pac[h][2] = ex2_h2(pack_f16x2(eB[0], eB[1]));
                pac[h][3] = ex2_h2(pack_f16x2(eB[2], eB[3]));
            }
        }

        #pragma unroll 4
        for (int t = 0; t < NTT; t++) {
            const int jj = t * 16;
            uint32_t pan[2][4];
            // ---- MUFU stream: P fragments for t+1 ----
            if (t + 1 < NTT) {
                const int jn = jj + 16;
                const uint32_t bq0 = sq16[sqo + jn];
                const uint32_t bq1 = sq16[sqo + jn + 8];
                #pragma unroll
                for (int h = 0; h < 2; h++) {
                    float eA[4] = {0.f, 0.f, 0.f, 0.f};
                    float eB[4] = {0.f, 0.f, 0.f, 0.f};
                    mma_f16k8(eA, ka[h][0], ka[h][1], bq0);
                    mma_f16k8(eB, ka[h][0], ka[h][1], bq1);
                    pan[h][0] = ex2_h2(pack_f16x2(eA[0], eA[1]));
                    pan[h][1] = ex2_h2(pack_f16x2(eA[2], eA[3]));
                    pan[h][2] = ex2_h2(pack_f16x2(eB[0], eB[1]));
                    pan[h][3] = ex2_h2(pack_f16x2(eB[2], eB[3]));
                }
            }
            // ---- tensor stream: mma2 batch for t ----
            #pragma unroll
            for (int p = 0; p < 4; p++) {
                uint32_t r0, r1, r2, r3;
                ldsm_x4(r0, r1, r2, r3, addrp[p] + (uint32_t)(jj * 2));
                #pragma unroll
                for (int h = 0; h < 2; h++) {
                    mma_f16(acc[h][2 * p],     pac[h][0], pac[h][1], pac[h][2], pac[h][3], r0, r1);
                    mma_f16(acc[h][2 * p + 1], pac[h][0], pac[h][1], pac[h][2], pac[h][3], r2, r3);
                }
            }
            if (t + 1 < NTT) {
                #pragma unroll
                for (int h = 0; h < 2; h++)
                    #pragma unroll
                    for (int s = 0; s < 4; s++) pac[h][s] = pan[h][s];
            }
        }
    }

    // epilogue: transpose [i][c] -> [c][i] via smem overlay, f16 global store
    __syncthreads();
    #pragma unroll
    for (int h = 0; h < 2; h++) {
        const int il = iw + h * 16;
        #pragma unroll
        for (int nc = 0; nc < 8; nc++) {
            strans[(nc * 8 + 2 * tg) * 264 + il + gp]         = acc[h][nc][0];
            strans[(nc * 8 + 2 * tg + 1) * 264 + il + gp]     = acc[h][nc][1];
            strans[(nc * 8 + 2 * tg) * 264 + il + gp + 8]     = acc[h][nc][2];
            strans[(nc * 8 + 2 * tg + 1) * 264 + il + gp + 8] = acc[h][nc][3];
        }
    }
    __syncthreads();
    #pragma unroll
    for (int t = 0; t < 16; t++) {
        const int idx = tid + t * 256;
        const int c = idx >> 6, f4 = idx & 63;
        const float4 v = *(const float4*)&strans[c * 264 + f4 * 4];
        uint2 o;
        o.x = pack_f16x2(v.x, v.y);
        o.y = pack_f16x2(v.z, v.w);
        *(uint2*)&g_opart16[jq][b][c][i_base + f4 * 4] = o;
    }
}

// ============================================================================
// combine: out = (gamma/2^12)*(op0+op1+op2+op3) + x  (fixed order, f16 parts)
// ============================================================================
__global__ void __launch_bounds__(256) combine_kernel(
    const float* __restrict__ x,
    const float* __restrict__ gamma,
    float* __restrict__ out)
{
    const int b = blockIdx.y;
    const size_t idx = ((size_t)blockIdx.x * 256 + threadIdx.x) * 4;
    const float gma = gamma[0] * (1.0f / VSCALE);
    const uint2 u0 = *(const uint2*)&g_opart16[0][b][0][idx];
    const uint2 u1 = *(const uint2*)&g_opart16[1][b][0][idx];
    const uint2 u2 = *(const uint2*)&g_opart16[2][b][0][idx];
    const uint2 u3 = *(const uint2*)&g_opart16[3][b][0][idx];
    const float4 xv = *(const float4*)&x[(size_t)b * CC * NN + idx];
    const float2 a0 = h2f(u0.x), a1 = h2f(u1.x), a2 = h2f(u2.x), a3 = h2f(u3.x);
    const float2 b0 = h2f(u0.y), b1 = h2f(u1.y), b2 = h2f(u2.y), b3 = h2f(u3.y);
    float4 o;
    o.x = gma * ((a0.x + a1.x) + (a2.x + a3.x)) + xv.x;
    o.y = gma * ((a0.y + a1.y) + (a2.y + a3.y)) + xv.y;
    o.z = gma * ((b0.x + b1.x) + (b2.x + b3.x)) + xv.z;
    o.w = gma * ((b0.y + b1.y) + (b2.y + b3.y)) + xv.w;
    *(float4*)&out[(size_t)b * CC * NN + idx] = o;
}

// ============================================================================
extern "C" void kernel_launch(void* const* d_in, const int* in_sizes, int n_in,
                              void* d_out, int out_size)
{
    const float* x     = (const float*)d_in[0];
    const float* wq    = (const float*)d_in[1];
    const float* bq    = (const float*)d_in[2];
    const float* wk    = (const float*)d_in[3];
    const float* bk    = (const float*)d_in[4];
    const float* wv    = (const float*)d_in[5];
    const float* bv    = (const float*)d_in[6];
    const float* gamma = (const float*)d_in[7];
    float* out = (float*)d_out;

    {
        dim3 grid(NN / 256, 5, BB);
        qkv_kernel<<<grid, 128>>>(x, wq, bq, wk, bk, wv, bv);
    }
    {
        dim3 grid(NN / 64, BB);
        zvpass_kernel<<<grid, 256>>>();
    }
    {
        const size_t stage_bytes = 4 * SQP32 * sizeof(uint32_t) + 64 * SVP * sizeof(__half);
        const size_t trans_bytes = 64 * 264 * sizeof(float);
        const size_t shmem = stage_bytes > trans_bytes ? stage_bytes : trans_bytes;
        cudaFuncSetAttribute(outpass_kernel,
                             cudaFuncAttributeMaxDynamicSharedMemorySize, (int)shmem);
        dim3 grid(NN / 256, 4, BB);
        outpass_kernel<<<grid, 256, shmem>>>();
    }
    {
        dim3 grid(CC * NN / 4 / 256, BB);
        combine_kernel<<<grid, 256>>>(x, gamma, out);
    }
}

// round 15
// speedup vs baseline: 1.0794x; 1.0794x over previous
#include <cuda_runtime.h>
#include <cuda_bf16.h>
#include <cuda_fp16.h>
#include <cstdint>

#define BB 2
#define CC 64
#define C8 8
#define NN 9216   // 96*96
#define L2E 1.4426950408889634f
#define VSCALE 4096.0f     // 2^12, pow2 -> exact unscale

// ---- scratch (static device globals; no allocation at runtime) ----
__device__ float g_q[BB][C8][NN];            // pre-scaled by log2(e)
__device__ float g_k[BB][C8][NN];
__device__ __half g_v16[BB][CC][NN];         // v (f16)
__device__ __half g_vp[BB][CC][NN];          // v' = v * rZ * 2^12  (fp16)
__device__ __half g_opart16[4][BB][CC][NN];  // partial outputs per j-quarter (f16)

// ---------------------------------------------------------------------------
// helpers
// ---------------------------------------------------------------------------
__device__ __forceinline__ uint32_t pack_f16x2(float lo, float hi) {
    uint32_t r;
    asm("cvt.rn.f16x2.f32 %0, %1, %2;" : "=r"(r) : "f"(hi), "f"(lo));
    return r;
}

__device__ __forceinline__ uint32_t ex2_h2(uint32_t h) {
    uint32_t r;
    asm("ex2.approx.f16x2 %0, %1;" : "=r"(r) : "r"(h));
    return r;
}

__device__ __forceinline__ uint32_t hadd2(uint32_t a, uint32_t b) {
    uint32_t r;
    asm("add.rn.f16x2 %0, %1, %2;" : "=r"(r) : "r"(a), "r"(b));
    return r;
}

__device__ __forceinline__ float2 h2f(uint32_t u) {
    return __half22float2(*reinterpret_cast<__half2*>(&u));
}

__device__ __forceinline__ void mma_tf32(float c[4],
                                         uint32_t a0, uint32_t a1, uint32_t a2, uint32_t a3,
                                         uint32_t b0, uint32_t b1) {
    asm volatile(
        "mma.sync.aligned.m16n8k8.row.col.f32.tf32.tf32.f32 "
        "{%0,%1,%2,%3}, {%4,%5,%6,%7}, {%8,%9}, {%0,%1,%2,%3};"
        : "+f"(c[0]), "+f"(c[1]), "+f"(c[2]), "+f"(c[3])
        : "r"(a0), "r"(a1), "r"(a2), "r"(a3), "r"(b0), "r"(b1));
}

__device__ __forceinline__ void mma_f16(float c[4],
                                        uint32_t a0, uint32_t a1, uint32_t a2, uint32_t a3,
                                        uint32_t b0, uint32_t b1) {
    asm volatile(
        "mma.sync.aligned.m16n8k16.row.col.f32.f16.f16.f32 "
        "{%0,%1,%2,%3}, {%4,%5,%6,%7}, {%8,%9}, {%0,%1,%2,%3};"
        : "+f"(c[0]), "+f"(c[1]), "+f"(c[2]), "+f"(c[3])
        : "r"(a0), "r"(a1), "r"(a2), "r"(a3), "r"(b0), "r"(b1));
}

__device__ __forceinline__ void ldsm_x4(uint32_t& r0, uint32_t& r1,
                                        uint32_t& r2, uint32_t& r3, uint32_t addr) {
    asm volatile("ldmatrix.sync.aligned.m8n8.x4.shared.b16 {%0,%1,%2,%3}, [%4];"
                 : "=r"(r0), "=r"(r1), "=r"(r2), "=r"(r3) : "r"(addr));
}

// ============================================================================
// Kernel 1: 1x1-conv projections, 5 groups of 16 output rows.
// g=0: q rows 0..7 (scaled by log2 e, f32) + k rows 0..7 (f32);
// g=1..4: v rows 16(g-1).. stored f16.
// ============================================================================
__global__ void __launch_bounds__(128) qkv_kernel(
    const float* __restrict__ x,
    const float* __restrict__ wq, const float* __restrict__ bq,
    const float* __restrict__ wk, const float* __restrict__ bk,
    const float* __restrict__ wv, const float* __restrict__ bv)
{
    __shared__ float sw[16][CC];
    __shared__ float sb[16];
    const int g = blockIdx.y;
    const int b = blockIdx.z;
    const int tid = threadIdx.x;

    for (int idx = tid; idx < 16 * CC; idx += 128) {
        const int row = idx >> 6, c = idx & 63;
        float val;
        if (g == 0) val = (row < 8) ? wq[row * CC + c] * L2E : wk[(row - 8) * CC + c];
        else        val = wv[(16 * (g - 1) + row) * CC + c];
        sw[row][c] = val;
    }
    if (tid < 16) {
        float bval;
        if (g == 0) bval = (tid < 8) ? bq[tid] * L2E : bk[tid - 8];
        else        bval = bv[16 * (g - 1) + tid];
        sb[tid] = bval;
    }
    __syncthreads();

    const int n0 = blockIdx.x * 256 + tid * 2;
    float2 acc[16];
    #pragma unroll
    for (int o = 0; o < 16; o++) { acc[o].x = sb[o]; acc[o].y = sb[o]; }
    const float* xb = x + (size_t)b * CC * NN;
    #pragma unroll 4
    for (int c = 0; c < CC; c++) {
        const float2 xv = *(const float2*)&xb[c * NN + n0];
        #pragma unroll
        for (int o = 0; o < 16; o++) {
            acc[o].x += sw[o][c] * xv.x;
            acc[o].y += sw[o][c] * xv.y;
        }
    }
    if (g == 0) {
        #pragma unroll
        for (int o = 0; o < 8; o++)  *(float2*)&g_q[b][o][n0] = acc[o];
        #pragma unroll
        for (int o = 0; o < 8; o++)  *(float2*)&g_k[b][o][n0] = acc[o + 8];
    } else {
        const int r0 = 16 * (g - 1);
        #pragma unroll
        for (int o = 0; o < 16; o++)
            *(uint32_t*)&g_v16[b][r0 + o][n0] = pack_f16x2(acc[o].x, acc[o].y);
    }
}

// ============================================================================
// zvpass: fused Z + v'. Block owns 64 j's, sweeps ALL i (72 chunks of 128):
// Z_j computed fully locally -> rZ -> v' slice converted in the same kernel.
// grid (144, BB), block 256, 2 blocks/SM. ex2 + accumulation in f16x2.
// ============================================================================
__global__ void __launch_bounds__(256) zvpass_kernel()
{
    __shared__ float skT[2][8 * 136];
    __shared__ float szw[8][64];
    __shared__ float srz[64];

    const int b = blockIdx.y;
    const int j_base = blockIdx.x * 64;
    const int tid = threadIdx.x;
    const int warp = tid >> 5, lane = tid & 31;
    const int gp = lane >> 2, tg = lane & 3;
    const int iw = warp * 16;

    // persistent q B-fragments: 8 n8 j-tiles
    uint32_t Bq0[8], Bq1[8];
    #pragma unroll
    for (int nt = 0; nt < 8; nt++) {
        const int j = j_base + nt * 8 + gp;
        Bq0[nt] = __float_as_uint(g_q[b][tg][j]);
        Bq1[nt] = __float_as_uint(g_q[b][tg + 4][j]);
    }

    uint32_t zaccH[8];
    #pragma unroll
    for (int m = 0; m < 8; m++) zaccH[m] = 0u;

    int so[4], si[4];
    #pragma unroll
    for (int t = 0; t < 4; t++) {
        const int e = tid + t * 256;
        so[t] = e >> 7; si[t] = e & 127;
    }

    const int NI = NN / 128;   // 72

    float pre[4];
    #pragma unroll
    for (int t = 0; t < 4; t++) pre[t] = g_k[b][so[t]][si[t]];
    #pragma unroll
    for (int t = 0; t < 4; t++) skT[0][so[t] * 136 + si[t]] = pre[t];
    __syncthreads();

    for (int it = 0; it < NI; it++) {
        if (it + 1 < NI) {
            const int ib = (it + 1) * 128;
            #pragma unroll
            for (int t = 0; t < 4; t++) pre[t] = g_k[b][so[t]][ib + si[t]];
        }
        const float* buf = skT[it & 1];
        const uint32_t a0 = __float_as_uint(buf[tg * 136 + iw + gp]);
        const uint32_t a1 = __float_as_uint(buf[tg * 136 + iw + gp + 8]);
        const uint32_t a2 = __float_as_uint(buf[(tg + 4) * 136 + iw + gp]);
        const uint32_t a3 = __float_as_uint(buf[(tg + 4) * 136 + iw + gp + 8]);

        #pragma unroll
        for (int nt = 0; nt < 8; nt++) {
            float e[4] = {0.f, 0.f, 0.f, 0.f};
            mma_tf32(e, a0, a1, a2, a3, Bq0[nt], Bq1[nt]);
            const uint32_t h01 = ex2_h2(pack_f16x2(e[0], e[1]));   // rows gp
            const uint32_t h23 = ex2_h2(pack_f16x2(e[2], e[3]));   // rows gp+8
            zaccH[nt] = hadd2(zaccH[nt], hadd2(h01, h23));
        }

        if (it + 1 < NI) {
            float* nbuf = skT[(it + 1) & 1];
            #pragma unroll
            for (int t = 0; t < 4; t++) nbuf[so[t] * 136 + si[t]] = pre[t];
            __syncthreads();
        }
    }

    // reduce over gp lanes (same tg share same j), f16x2
    #pragma unroll
    for (int nt = 0; nt < 8; nt++) {
        uint32_t v = zaccH[nt];
        v = hadd2(v, __shfl_xor_sync(~0u, v, 4));
        v = hadd2(v, __shfl_xor_sync(~0u, v, 8));
        v = hadd2(v, __shfl_xor_sync(~0u, v, 16));
        if (gp == 0) {
            const float2 f = h2f(v);
            szw[warp][nt * 8 + 2 * tg]     = f.x;
            szw[warp][nt * 8 + 2 * tg + 1] = f.y;
        }
    }
    __syncthreads();
    if (tid < 64) {
        float z = 0.f;
        #pragma unroll
        for (int w = 0; w < 8; w++) z += szw[w][tid];
        srz[tid] = VSCALE / z;
    }
    __syncthreads();

    // fused v': this block's 64-j slice (half2 pairs: 64c x 32 j-pairs)
    #pragma unroll
    for (int t = 0; t < 8; t++) {
        const int idx = tid + t * 256;
        const int c = idx >> 5, jp = idx & 31;
        const int j2 = jp * 2;
        const uint32_t vv = *(const uint32_t*)&g_v16[b][c][j_base + j2];
        const float2 vf = h2f(vv);
        *(uint32_t*)&g_vp[b][c][j_base + j2] =
            pack_f16x2(vf.x * srz[j2], vf.y * srz[j2 + 1]);
    }
}

// ============================================================================
// outpass: opart[jq][b][c][i] = sum over j-quarter of v'[c,j]*2^(q_j.k_i)
// grid (36, 4, BB), block 256, m=32/warp, ldmatrix.x4, f16 mma. (R13 proven)
// ============================================================================
#define SQP 264   // f32 pitch for sq
#define SVP 264   // f16 pitch for sv

__global__ void __launch_bounds__(256, 2) outpass_kernel()
{
    extern __shared__ float sm[];
    float* sq = sm;                              // [8][SQP] f32
    __half* sv = (__half*)(sm + 8 * SQP);        // [64][SVP]
    float* strans = sm;                          // epilogue overlay [64][264]

    const int b = blockIdx.z;
    const int jq = blockIdx.y;
    const int i_base = blockIdx.x * 256;
    const int tid = threadIdx.x;
    const int warp = tid >> 5, lane = tid & 31;
    const int gp = lane >> 2, tg = lane & 3;
    const int iw = warp * 32;

    uint32_t ak[2][4];
    #pragma unroll
    for (int h = 0; h < 2; h++) {
        const int ib = i_base + iw + h * 16;
        ak[h][0] = __float_as_uint(g_k[b][tg][ib + gp]);
        ak[h][1] = __float_as_uint(g_k[b][tg][ib + gp + 8]);
        ak[h][2] = __float_as_uint(g_k[b][tg + 4][ib + gp]);
        ak[h][3] = __float_as_uint(g_k[b][tg + 4][ib + gp + 8]);
    }

    float acc[2][8][4];
    #pragma unroll
    for (int h = 0; h < 2; h++)
        #pragma unroll
        for (int nc = 0; nc < 8; nc++)
            #pragma unroll
            for (int s = 0; s < 4; s++) acc[h][nc][s] = 0.f;

    uint32_t sv_u32;
    asm("{ .reg .u64 t; cvta.to.shared.u64 t, %1; cvt.u32.u64 %0, t; }"
        : "=r"(sv_u32) : "l"(sv));
    const int mrow = ((lane >> 4) << 3) + (lane & 7);
    const int mcol = ((lane >> 3) & 1) * 8;

    uint32_t addrp[4];
    #pragma unroll
    for (int p = 0; p < 4; p++)
        addrp[p] = sv_u32 + (uint32_t)(((p * 16 + mrow) * SVP + mcol) * 2);
    const int sqo0 = tg * SQP + gp;
    const int sqo1 = (tg + 4) * SQP + gp;

    const int j0q = jq * (NN / 4);
    for (int sc = 0; sc < NN / 4 / 256; sc++) {
        const int jb = j0q + sc * 256;
        __syncthreads();
        #pragma unroll
        for (int t = 0; t < 2; t++) {
            const int idx = tid + t * 256;
            const int o = idx >> 6, c4 = idx & 63;
            *(float4*)&sq[o * SQP + c4 * 4] = *(const float4*)&g_q[b][o][jb + c4 * 4];
        }
        #pragma unroll
        for (int t = 0; t < 8; t++) {
            const int idx = tid + t * 256;
            const int row = idx >> 5, q8 = idx & 31;
            *(uint4*)&sv[row * SVP + q8 * 8] = *(const uint4*)&g_vp[b][row][jb + q8 * 8];
        }
        __syncthreads();

        uint32_t pac[2][4];
        {
            const uint32_t B0a = __float_as_uint(sq[sqo0]);
            const uint32_t B1a = __float_as_uint(sq[sqo1]);
            const uint32_t B0b = __float_as_uint(sq[sqo0 + 8]);
            const uint32_t B1b = __float_as_uint(sq[sqo1 + 8]);
            #pragma unroll
            for (int h = 0; h < 2; h++) {
                float eA[4] = {0.f, 0.f, 0.f, 0.f};
                float eB[4] = {0.f, 0.f, 0.f, 0.f};
                mma_tf32(eA, ak[h][0], ak[h][1], ak[h][2], ak[h][3], B0a, B1a);
                mma_tf32(eB, ak[h][0], ak[h][1], ak[h][2], ak[h][3], B0b, B1b);
                pac[h][0] = ex2_h2(pack_f16x2(eA[0], eA[1]));
                pac[h][1] = ex2_h2(pack_f16x2(eA[2], eA[3]));
                pac[h][2] = ex2_h2(pack_f16x2(eB[0], eB[1]));
                pac[h][3] = ex2_h2(pack_f16x2(eB[2], eB[3]));
            }
        }

        #pragma unroll 4
        for (int t = 0; t < 16; t++) {
            const int jj = t * 16;
            uint32_t pan[2][4];
            if (t + 1 < 16) {
                const int jn = jj + 16;
                const uint32_t B0a = __float_as_uint(sq[sqo0 + jn]);
                const uint32_t B1a = __float_as_uint(sq[sqo1 + jn]);
                const uint32_t B0b = __float_as_uint(sq[sqo0 + jn + 8]);
                const uint32_t B1b = __float_as_uint(sq[sqo1 + jn + 8]);
                #pragma unroll
                for (int h = 0; h < 2; h++) {
                    float eA[4] = {0.f, 0.f, 0.f, 0.f};
                    float eB[4] = {0.f, 0.f, 0.f, 0.f};
                    mma_tf32(eA, ak[h][0], ak[h][1], ak[h][2], ak[h][3], B0a, B1a);
                    mma_tf32(eB, ak[h][0], ak[h][1], ak[h][2], ak[h][3], B0b, B1b);
                    pan[h][0] = ex2_h2(pack_f16x2(eA[0], eA[1]));
                    pan[h][1] = ex2_h2(pack_f16x2(eA[2], eA[3]));
                    pan[h][2] = ex2_h2(pack_f16x2(eB[0], eB[1]));
                    pan[h][3] = ex2_h2(pack_f16x2(eB[2], eB[3]));
                }
            }
            #pragma unroll
            for (int p = 0; p < 4; p++) {
                uint32_t r0, r1, r2, r3;
                ldsm_x4(r0, r1, r2, r3, addrp[p] + (uint32_t)(jj * 2));
                #pragma unroll
                for (int h = 0; h < 2; h++) {
                    mma_f16(acc[h][2 * p],     pac[h][0], pac[h][1], pac[h][2], pac[h][3], r0, r1);
                    mma_f16(acc[h][2 * p + 1], pac[h][0], pac[h][1], pac[h][2], pac[h][3], r2, r3);
                }
            }
            if (t + 1 < 16) {
                #pragma unroll
                for (int h = 0; h < 2; h++)
                    #pragma unroll
                    for (int s = 0; s < 4; s++) pac[h][s] = pan[h][s];
            }
        }
    }

    // epilogue: transpose [i][c] -> [c][i] via smem overlay, f16 global store
    __syncthreads();
    #pragma unroll
    for (int h = 0; h < 2; h++) {
        const int il = iw + h * 16;
        #pragma unroll
        for (int nc = 0; nc < 8; nc++) {
            strans[(nc * 8 + 2 * tg) * 264 + il + gp]         = acc[h][nc][0];
            strans[(nc * 8 + 2 * tg + 1) * 264 + il + gp]     = acc[h][nc][1];
            strans[(nc * 8 + 2 * tg) * 264 + il + gp + 8]     = acc[h][nc][2];
            strans[(nc * 8 + 2 * tg + 1) * 264 + il + gp + 8] = acc[h][nc][3];
        }
    }
    __syncthreads();
    #pragma unroll
    for (int t = 0; t < 16; t++) {
        const int idx = tid + t * 256;
        const int c = idx >> 6, f4 = idx & 63;
        const float4 v = *(const float4*)&strans[c * 264 + f4 * 4];
        uint2 o;
        o.x = pack_f16x2(v.x, v.y);
        o.y = pack_f16x2(v.z, v.w);
        *(uint2*)&g_opart16[jq][b][c][i_base + f4 * 4] = o;
    }
}

// ============================================================================
// combine: out = (gamma/2^12)*(op0+op1+op2+op3) + x  (fixed order, f16 parts)
// ============================================================================
__global__ void __launch_bounds__(256) combine_kernel(
    const float* __restrict__ x,
    const float* __restrict__ gamma,
    float* __restrict__ out)
{
    const int b = blockIdx.y;
    const size_t idx = ((size_t)blockIdx.x * 256 + threadIdx.x) * 4;
    const float gma = gamma[0] * (1.0f / VSCALE);
    const uint2 u0 = *(const uint2*)&g_opart16[0][b][0][idx];
    const uint2 u1 = *(const uint2*)&g_opart16[1][b][0][idx];
    const uint2 u2 = *(const uint2*)&g_opart16[2][b][0][idx];
    const uint2 u3 = *(const uint2*)&g_opart16[3][b][0][idx];
    const float4 xv = *(const float4*)&x[(size_t)b * CC * NN + idx];
    const float2 a0 = h2f(u0.x), a1 = h2f(u1.x), a2 = h2f(u2.x), a3 = h2f(u3.x);
    const float2 b0 = h2f(u0.y), b1 = h2f(u1.y), b2 = h2f(u2.y), b3 = h2f(u3.y);
    float4 o;
    o.x = gma * ((a0.x + a1.x) + (a2.x + a3.x)) + xv.x;
    o.y = gma * ((a0.y + a1.y) + (a2.y + a3.y)) + xv.y;
    o.z = gma * ((b0.x + b1.x) + (b2.x + b3.x)) + xv.z;
    o.w = gma * ((b0.y + b1.y) + (b2.y + b3.y)) + xv.w;
    *(float4*)&out[(size_t)b * CC * NN + idx] = o;
}

// ============================================================================
extern "C" void kernel_launch(void* const* d_in, const int* in_sizes, int n_in,
                              void* d_out, int out_size)
{
    const float* x     = (const float*)d_in[0];
    const float* wq    = (const float*)d_in[1];
    const float* bq    = (const float*)d_in[2];
    const float* wk    = (const float*)d_in[3];
    const float* bk    = (const float*)d_in[4];
    const float* wv    = (const float*)d_in[5];
    const float* bv    = (const float*)d_in[6];
    const float* gamma = (const float*)d_in[7];
    float* out = (float*)d_out;

    {
        dim3 grid(NN / 256, 5, BB);
        qkv_kernel<<<grid, 128>>>(x, wq, bq, wk, bk, wv, bv);
    }
    {
        dim3 grid(NN / 64, BB);
        zvpass_kernel<<<grid, 256>>>();
    }
    {
        const size_t stage_bytes = 8 * SQP * sizeof(float) + 64 * SVP * sizeof(__half);
        const size_t trans_bytes = 64 * 264 * sizeof(float);
        const size_t shmem = stage_bytes > trans_bytes ? stage_bytes : trans_bytes;
        cudaFuncSetAttribute(outpass_kernel,
                             cudaFuncAttributeMaxDynamicSharedMemorySize, (int)shmem);
        dim3 grid(NN / 256, 4, BB);
        outpass_kernel<<<grid, 256, shmem>>>();
    }
    {
        dim3 grid(CC * NN / 4 / 256, BB);
        combine_kernel<<<grid, 256>>>(x, gamma, out);
    }
}